// round 4
// baseline (speedup 1.0000x reference)
#include <cuda_runtime.h>
#include <math.h>
#include <stdint.h>

// Problem dims
#define BB 32    // batch
#define TT 512   // time
#define II 512   // input size
#define HH 1024  // hidden (cell) size
#define RR 512   // recurrent/projection size

#define NBLK 256 // persistent grid (co-resident: <= 148 SMs * 2 blocks)
#define NTHR 256

// ---------------------------------------------------------------------------
// Scratch (__device__ globals; no allocations anywhere)
// ---------------------------------------------------------------------------
__device__ float  g_xT[(size_t)TT * II * BB];     // [t][i][b]
__device__ float4 g_Wc0[(size_t)1024 * HH];       // [k][j] float4(i,f,g,o)
__device__ float4 g_Wc1[(size_t)1024 * HH];
__device__ float  g_WpT0[(size_t)HH * RR];        // [k][r]
__device__ float  g_WpT1[(size_t)HH * RR];
__device__ float  g_h0T[RR * BB];                 // [r][b]
__device__ float  g_h1T[RR * BB];
__device__ float  g_c0T[HH * BB];                 // [h][b]
__device__ float  g_c1T[HH * BB];
__device__ float  g_m0T[HH * BB];                 // [h][b]
__device__ float  g_m1T[HH * BB];

// ---------------------------------------------------------------------------
// Software grid barrier (sense-reversal; all NBLK blocks co-resident)
// ---------------------------------------------------------------------------
__device__ unsigned g_bar_count = 0;
__device__ volatile unsigned g_bar_gen = 0;

__device__ __forceinline__ void grid_barrier() {
    __syncthreads();
    if (threadIdx.x == 0) {
        unsigned gen = g_bar_gen;     // read BEFORE arriving (release can't happen yet)
        __threadfence();              // publish phase data + order the read above
        if (atomicAdd(&g_bar_count, 1u) == NBLK - 1u) {
            g_bar_count = 0;
            __threadfence();
            g_bar_gen = gen + 1u;     // release
        } else {
            while (g_bar_gen == gen) { __nanosleep(64); }
        }
        __threadfence();              // acquire
    }
    __syncthreads();
}

// ---------------------------------------------------------------------------
// Packed fp32x2 helpers (Blackwell fma.rn.f32x2 — 2x fp32 FMA throughput)
// ---------------------------------------------------------------------------
__device__ __forceinline__ void ffma2(unsigned long long& acc,
                                      unsigned long long a, unsigned long long b) {
    asm("fma.rn.f32x2 %0, %1, %2, %0;" : "+l"(acc) : "l"(a), "l"(b));
}
__device__ __forceinline__ unsigned long long splat2(float v) {
    unsigned long long r;
    asm("mov.b64 %0, {%1, %1};" : "=l"(r) : "f"(v));
    return r;
}

// ---------------------------------------------------------------------------
// One persistent kernel = one graph node. Does: zero state, transpose x,
// pack weights, then 513 supersteps (layer wavefront) with grid barriers.
// ---------------------------------------------------------------------------
__global__ void __launch_bounds__(NTHR, 2)
lstm_persistent(const float* __restrict__ x,
                const float* __restrict__ Wih0, const float* __restrict__ Whh0,
                const float* __restrict__ bias0, const float* __restrict__ Wp0,
                const float* __restrict__ Wih1, const float* __restrict__ Whh1,
                const float* __restrict__ bias1, const float* __restrict__ Wp1,
                float* __restrict__ out)
{
    __shared__ __align__(16) unsigned char smraw[32768];
    const int tid  = threadIdx.x;
    const int warp = tid >> 5;
    const int lane = tid & 31;
    const int blk  = blockIdx.x;

    // ---- prologue: zero recurrent state (graph is replayed; must re-zero) ----
    for (int i = blk * NTHR + tid; i < HH * BB; i += NBLK * NTHR) {
        g_c0T[i] = 0.f; g_c1T[i] = 0.f;
        if (i < RR * BB) { g_h0T[i] = 0.f; g_h1T[i] = 0.f; }
    }

    // ---- prologue: transpose x [b][t][i] -> xT[t][i][b] (8192 32x32 tiles) ----
    {
        float (*sm)[33] = (float(*)[33])smraw;
        for (int tile = blk; tile < 16 * TT; tile += NBLK) {
            const int i0 = (tile & 15) * 32;
            const int t  = tile >> 4;
            __syncthreads();
            #pragma unroll
            for (int p = 0; p < 4; ++p) {
                const int ii = tid & 31, b = (tid >> 5) + p * 8;
                sm[ii][b] = x[((size_t)b * TT + t) * II + i0 + ii];
            }
            __syncthreads();
            #pragma unroll
            for (int p = 0; p < 4; ++p) {
                const int b = tid & 31, ii = (tid >> 5) + p * 8;
                g_xT[((size_t)t * II + i0 + ii) * BB + b] = sm[ii][b];
            }
        }
    }

    // ---- prologue: pack gate weights Wc[k][j] = float4(i,f,g,o) ----
    // k<512 -> W_ih row k; k>=512 -> W_hh row k-512 (both have 512 cols here).
    {
        float (*sm)[32][33] = (float(*)[32][33])smraw;  // [4][32][33]
        for (int tile = blk; tile < 2 * 32 * 32; tile += NBLK) {
            const int layer = tile >> 10;
            const int j0 = ((tile >> 5) & 31) * 32;
            const int k0 = (tile & 31) * 32;
            const float* Wih = layer ? Wih1 : Wih0;
            const float* Whh = layer ? Whh1 : Whh0;
            float4* dst = layer ? g_Wc1 : g_Wc0;
            const float* src = (k0 < 512) ? Wih : Whh;
            const int ks0 = (k0 < 512) ? k0 : (k0 - 512);
            __syncthreads();
            #pragma unroll
            for (int it = 0; it < 16; ++it) {
                const int idx = it * NTHR + tid;
                const int kk = idx & 31, jj = (idx >> 5) & 31, g = idx >> 10;
                sm[g][jj][kk] = src[((size_t)(g * HH + j0 + jj)) * 512 + ks0 + kk];
            }
            __syncthreads();
            #pragma unroll
            for (int it = 0; it < 4; ++it) {
                const int idx = it * NTHR + tid;
                const int jj = idx & 31, kk = idx >> 5;
                dst[(size_t)(k0 + kk) * HH + j0 + jj] =
                    make_float4(sm[0][jj][kk], sm[1][jj][kk], sm[2][jj][kk], sm[3][jj][kk]);
            }
        }
    }

    // ---- prologue: pack WpT[k][r] = Wp[r][k] ----
    {
        float (*sm)[33] = (float(*)[33])smraw;
        for (int tile = blk; tile < 2 * 16 * 32; tile += NBLK) {
            const int layer = tile >> 9;
            const int r0 = ((tile >> 5) & 15) * 32;
            const int k0 = (tile & 31) * 32;
            const float* Wp = layer ? Wp1 : Wp0;
            float* dst = layer ? g_WpT1 : g_WpT0;
            __syncthreads();
            #pragma unroll
            for (int it = 0; it < 4; ++it) {
                const int idx = it * NTHR + tid;
                const int kk = idx & 31, rr = idx >> 5;
                sm[rr][kk] = Wp[(size_t)(r0 + rr) * HH + k0 + kk];
            }
            __syncthreads();
            #pragma unroll
            for (int it = 0; it < 4; ++it) {
                const int idx = it * NTHR + tid;
                const int rr = idx & 31, kk = idx >> 5;
                dst[(size_t)(k0 + kk) * RR + r0 + rr] = sm[rr][kk];
            }
        }
    }

    grid_barrier();

    // ---- unit decode (fixed per block across all supersteps) ----
    // Gates unit: (layer, j-tile of 32 hidden, batch group of 8). 256 units.
    const int g_layer = blk >> 7;
    const int g_j0 = ((blk >> 2) & 31) * 32;
    const int g_b0 = (blk & 3) * 8;
    const float4* __restrict__ g_Wc = g_layer ? g_Wc1 : g_Wc0;
    const float*  __restrict__ g_bias = g_layer ? bias1 : bias0;
    float* g_cT = g_layer ? g_c1T : g_c0T;
    float* g_mT = g_layer ? g_m1T : g_m0T;

    // Proj unit: (layer, r-tile of 32, batch group of 8). 128 units.
    const bool p_valid = blk < 128;
    const int p_layer = (blk >> 6) & 1;
    const int p_r0 = ((blk >> 2) & 15) * 32;
    const int p_b0 = (blk & 3) * 8;
    const float* __restrict__ p_mT  = p_layer ? g_m1T : g_m0T;
    const float* __restrict__ p_WpT = p_layer ? g_WpT1 : g_WpT0;
    float* p_hT = p_layer ? g_h1T : g_h0T;

    // ---- main recurrence: wavefront layer0 @ t=s, layer1 @ t=s-1 ----
    for (int s = 0; s <= TT; ++s) {
        // ===== phase 1: gates + cell update =====
        const int tg = g_layer ? (s - 1) : s;
        if ((unsigned)tg < TT) {
            const int kg = warp * 128;  // 8-warp k-split of k=1024
            const float* inp;
            if (g_layer == 0)
                inp = (kg < 512) ? (g_xT + ((size_t)tg * II + kg) * BB)
                                 : (g_h0T + (size_t)(kg - 512) * BB);
            else
                inp = (kg < 512) ? (g_h0T + (size_t)kg * BB)
                                 : (g_h1T + (size_t)(kg - 512) * BB);
            inp += g_b0;
            const float4* wp = g_Wc + (size_t)kg * HH + g_j0 + lane;

            unsigned long long acc[4][4];  // [gate][batch-pair]
            #pragma unroll
            for (int g = 0; g < 4; ++g)
                #pragma unroll
                for (int p = 0; p < 4; ++p) acc[g][p] = 0ull;

            #pragma unroll 4
            for (int k = 0; k < 128; ++k) {
                const float4 w = __ldg(wp + (size_t)k * HH);              // 32 j's coalesced
                const ulonglong2 hA = __ldg((const ulonglong2*)(inp + (size_t)k * BB));
                const ulonglong2 hB = __ldg((const ulonglong2*)(inp + (size_t)k * BB + 4));
                const unsigned long long w0 = splat2(w.x), w1 = splat2(w.y);
                const unsigned long long w2 = splat2(w.z), w3 = splat2(w.w);
                ffma2(acc[0][0], w0, hA.x); ffma2(acc[0][1], w0, hA.y);
                ffma2(acc[0][2], w0, hB.x); ffma2(acc[0][3], w0, hB.y);
                ffma2(acc[1][0], w1, hA.x); ffma2(acc[1][1], w1, hA.y);
                ffma2(acc[1][2], w1, hB.x); ffma2(acc[1][3], w1, hB.y);
                ffma2(acc[2][0], w2, hA.x); ffma2(acc[2][1], w2, hA.y);
                ffma2(acc[2][2], w2, hB.x); ffma2(acc[2][3], w2, hB.y);
                ffma2(acc[3][0], w3, hA.x); ffma2(acc[3][1], w3, hA.y);
                ffma2(acc[3][2], w3, hB.x); ffma2(acc[3][3], w3, hB.y);
            }

            unsigned long long (*smg)[32][4][4] =
                (unsigned long long(*)[32][4][4])smraw;  // [warp][j][gate][pair] 32 KB
            #pragma unroll
            for (int g = 0; g < 4; ++g)
                #pragma unroll
                for (int p = 0; p < 4; ++p)
                    smg[warp][lane][g][p] = acc[g][p];
            __syncthreads();

            // reduce across 8 warps + cell update. thread -> (j = tid>>3, b = tid&7)
            {
                const int j = tid >> 3, b = tid & 7;
                const float* sf = (const float*)smraw;
                float gv[4];
                #pragma unroll
                for (int g = 0; g < 4; ++g) {
                    float v = g_bias[g * HH + g_j0 + j];
                    #pragma unroll
                    for (int w8 = 0; w8 < 8; ++w8)
                        v += sf[(w8 * 128 + j * 4 + g) * 8 + b];
                    gv[g] = v;
                }
                const float ig = 1.f / (1.f + expf(-gv[0]));
                const float fg = 1.f / (1.f + expf(-gv[1]));
                const float gg = tanhf(gv[2]);
                const float og = 1.f / (1.f + expf(-gv[3]));
                const int ci = (g_j0 + j) * BB + g_b0 + b;
                const float c = fg * g_cT[ci] + ig * gg;
                g_cT[ci] = c;
                g_mT[ci] = og * tanhf(c);
            }
        }
        grid_barrier();

        // ===== phase 2: projection h = m @ Wp^T (+ output for layer 1) =====
        const int tp = p_layer ? (s - 1) : s;
        if (p_valid && (unsigned)tp < TT) {
            const int kg = warp * 128;
            const float* inp = p_mT + (size_t)kg * BB + p_b0;
            const float* wpp = p_WpT + (size_t)kg * RR + p_r0 + lane;

            unsigned long long acc[4] = {0ull, 0ull, 0ull, 0ull};
            #pragma unroll 4
            for (int k = 0; k < 128; ++k) {
                const float w = __ldg(wpp + (size_t)k * RR);
                const ulonglong2 hA = __ldg((const ulonglong2*)(inp + (size_t)k * BB));
                const ulonglong2 hB = __ldg((const ulonglong2*)(inp + (size_t)k * BB + 4));
                const unsigned long long ws = splat2(w);
                ffma2(acc[0], ws, hA.x); ffma2(acc[1], ws, hA.y);
                ffma2(acc[2], ws, hB.x); ffma2(acc[3], ws, hB.y);
            }
            unsigned long long (*smp)[32][4] = (unsigned long long(*)[32][4])smraw;
            #pragma unroll
            for (int p = 0; p < 4; ++p) smp[warp][lane][p] = acc[p];
            __syncthreads();

            const int r = tid & 31, b = tid >> 5;
            const float* sf = (const float*)smraw;
            float v = 0.f;
            #pragma unroll
            for (int w8 = 0; w8 < 8; ++w8)
                v += sf[(w8 * 32 + r) * 8 + b];
            p_hT[(p_r0 + r) * BB + p_b0 + b] = v;
            if (p_layer)
                out[((size_t)(p_b0 + b) * TT + tp) * RR + p_r0 + r] = v;
        }
        grid_barrier();
    }
}

// ---------------------------------------------------------------------------
// Launch: ONE kernel node (minimizes graph upload footprint; the 1029-node
// graph left a 2 MB driver upload buffer live after teardown -> rule fail).
// ---------------------------------------------------------------------------
extern "C" void kernel_launch(void* const* d_in, const int* in_sizes, int n_in,
                              void* d_out, int out_size) {
    const float* x    = (const float*)d_in[0];
    const float* Wih0 = (const float*)d_in[1];
    const float* Whh0 = (const float*)d_in[2];
    const float* b0   = (const float*)d_in[3];
    const float* Wp0  = (const float*)d_in[4];
    const float* Wih1 = (const float*)d_in[5];
    const float* Whh1 = (const float*)d_in[6];
    const float* b1   = (const float*)d_in[7];
    const float* Wp1  = (const float*)d_in[8];
    float* out = (float*)d_out;

    lstm_persistent<<<NBLK, NTHR>>>(x, Wih0, Whh0, b0, Wp0,
                                    Wih1, Whh1, b1, Wp1, out);
}